// round 4
// baseline (speedup 1.0000x reference)
#include <cuda_runtime.h>
#include <cuda_bf16.h>
#include <cstdint>
#include <math.h>

// Problem constants
#define B_   2
#define S_   4096
#define E_   768
#define H_   12
#define DK_  64
#define BH_  (B_ * H_)          // 24
#define ROWS_ (B_ * S_)         // 8192

// ---------------- scratch (device globals; no allocation allowed) -----------
__device__ float g_Q[BH_ * S_ * DK_];    // [bh][s][d], pre-scaled by 1/8
__device__ float g_K[BH_ * S_ * DK_];
__device__ float g_V[BH_ * S_ * DK_];
__device__ float g_AO[ROWS_ * E_];       // attention output, [b*s][e]

// ---------------- mma.sync tf32 helpers -------------------------------------
__device__ __forceinline__ uint32_t f2tf(float x) {
    uint32_t u;
    asm("cvt.rna.tf32.f32 %0, %1;" : "=r"(u) : "f"(x));
    return u;
}
__device__ __forceinline__ uint4 cvt4(float4 v) {
    return make_uint4(f2tf(v.x), f2tf(v.y), f2tf(v.z), f2tf(v.w));
}
__device__ __forceinline__ void mma_tf32(float* d,
                                         uint32_t a0, uint32_t a1,
                                         uint32_t a2, uint32_t a3,
                                         uint32_t b0, uint32_t b1) {
    asm volatile(
        "mma.sync.aligned.m16n8k8.row.col.f32.tf32.tf32.f32 "
        "{%0,%1,%2,%3}, {%4,%5,%6,%7}, {%8,%9}, {%0,%1,%2,%3};"
        : "+f"(d[0]), "+f"(d[1]), "+f"(d[2]), "+f"(d[3])
        : "r"(a0), "r"(a1), "r"(a2), "r"(a3), "r"(b0), "r"(b1));
}

// ---------------- GEMM: C = A[8192,768] @ W[768,768] (tf32 mma) -------------
// BM=128, BN=128, BK=16, double-buffered smem + register prefetch.
#define AP 20
#define BP 136

__global__ __launch_bounds__(256, 2)
void gemm_tc(const float* __restrict__ X,
             const float* __restrict__ W0,
             const float* __restrict__ W1,
             const float* __restrict__ W2,
             float* __restrict__ Out,
             int mode)
{
    __shared__ uint32_t As[2][128 * AP];
    __shared__ uint32_t Bs[2][16 * BP];

    const float* A;
    const float* W;
    float* Dst = nullptr;
    float scale = 1.0f;
    if (mode == 1) {
        A = X;
        int z = blockIdx.z;
        W   = (z == 0) ? W0 : (z == 1) ? W1 : W2;
        Dst = (z == 0) ? g_Q : (z == 1) ? g_K : g_V;
        if (z == 0) scale = 0.125f;
    } else {
        A = g_AO;
        W = W0;
    }

    const int tid  = threadIdx.x;
    const int lane = tid & 31;
    const int wid  = tid >> 5;
    const int wm   = wid >> 2;
    const int wn   = wid & 3;
    const int cq   = lane >> 2;
    const int j    = lane & 3;
    const int row0 = blockIdx.y * 128;
    const int col0 = blockIdx.x * 128;

    // per-thread load coords
    const int ar0 = tid >> 2, ac4 = tid & 3;         // +256: ar0+64
    const int bk0 = tid >> 5, bc4 = tid & 31;        // +256: bk0+8

    float acc[4][4][4];
#pragma unroll
    for (int mi = 0; mi < 4; mi++)
#pragma unroll
        for (int ni = 0; ni < 4; ni++)
#pragma unroll
            for (int q = 0; q < 4; q++) acc[mi][ni][q] = 0.0f;

    // prologue: tile k0=0 -> buf 0
    {
#pragma unroll
        for (int i = 0; i < 2; i++) {
            int r = ar0 + i * 64;
            float4 v = *(const float4*)&A[(size_t)(row0 + r) * E_ + ac4 * 4];
            *(uint4*)&As[0][r * AP + ac4 * 4] = cvt4(v);
        }
#pragma unroll
        for (int i = 0; i < 2; i++) {
            int kr = bk0 + i * 8;
            float4 v = *(const float4*)&W[(size_t)kr * E_ + col0 + bc4 * 4];
            *(uint4*)&Bs[0][kr * BP + bc4 * 4] = cvt4(v);
        }
    }
    __syncthreads();

    for (int k0 = 0; k0 < E_; k0 += 16) {
        const int p = (k0 >> 4) & 1;
        const bool pf = (k0 + 16 < E_);
        float4 apre[2], bpre[2];
        if (pf) {
#pragma unroll
            for (int i = 0; i < 2; i++)
                apre[i] = *(const float4*)&A[(size_t)(row0 + ar0 + i * 64) * E_ + k0 + 16 + ac4 * 4];
#pragma unroll
            for (int i = 0; i < 2; i++)
                bpre[i] = *(const float4*)&W[(size_t)(k0 + 16 + bk0 + i * 8) * E_ + col0 + bc4 * 4];
        }

#pragma unroll
        for (int ks = 0; ks < 16; ks += 8) {
            uint32_t af[4][4], bf[4][2];
#pragma unroll
            for (int mi = 0; mi < 4; mi++) {
                int row = wm * 64 + mi * 16 + cq;
                int ka  = ks + j;
                af[mi][0] = As[p][row * AP + ka];
                af[mi][1] = As[p][(row + 8) * AP + ka];
                af[mi][2] = As[p][row * AP + ka + 4];
                af[mi][3] = As[p][(row + 8) * AP + ka + 4];
            }
#pragma unroll
            for (int ni = 0; ni < 4; ni++) {
                int col = wn * 32 + ni * 8 + cq;
                bf[ni][0] = Bs[p][(ks + j) * BP + col];
                bf[ni][1] = Bs[p][(ks + 4 + j) * BP + col];
            }
#pragma unroll
            for (int mi = 0; mi < 4; mi++)
#pragma unroll
                for (int ni = 0; ni < 4; ni++)
                    mma_tf32(acc[mi][ni], af[mi][0], af[mi][1], af[mi][2], af[mi][3],
                             bf[ni][0], bf[ni][1]);
        }

        if (pf) {
#pragma unroll
            for (int i = 0; i < 2; i++)
                *(uint4*)&As[1 - p][(ar0 + i * 64) * AP + ac4 * 4] = cvt4(apre[i]);
#pragma unroll
            for (int i = 0; i < 2; i++)
                *(uint4*)&Bs[1 - p][(bk0 + i * 8) * BP + bc4 * 4] = cvt4(bpre[i]);
        }
        __syncthreads();
    }

#pragma unroll
    for (int mi = 0; mi < 4; mi++) {
#pragma unroll
        for (int ni = 0; ni < 4; ni++) {
            int r_   = row0 + wm * 64 + mi * 16 + cq;
            int col  = col0 + wn * 32 + ni * 8 + 2 * j;
            float2 v0 = make_float2(acc[mi][ni][0] * scale, acc[mi][ni][1] * scale);
            float2 v1 = make_float2(acc[mi][ni][2] * scale, acc[mi][ni][3] * scale);
            if (mode == 1) {
                int h  = col >> 6;
                int d0 = col & 63;
                int b0b = r_ >> 12, s0s = r_ & (S_ - 1);
                *(float2*)&Dst[(((size_t)b0b * H_ + h) * S_ + s0s) * DK_ + d0] = v0;
                int r1 = r_ + 8;
                int b1b = r1 >> 12, s1s = r1 & (S_ - 1);
                *(float2*)&Dst[(((size_t)b1b * H_ + h) * S_ + s1s) * DK_ + d0] = v1;
            } else {
                *(float2*)&Out[(size_t)r_ * E_ + col] = v0;
                *(float2*)&Out[(size_t)(r_ + 8) * E_ + col] = v1;
            }
        }
    }
}

// ---------------- flash attention v2: Q-in-regs, shuffle-free PV -------------
// CTA: 256 q-rows x 1 head, 8 warps x 32 q-rows (2 m-tiles). KV tile = 64.
// S = Q K^T with permuted k (slot j -> 4j+c within 16-groups, LDG.128/LDS.128).
// PV computes O^T = V^T P^T with kv-permutation (j -> 2j, j+4 -> 2j+1) so the
// S C-fragment is directly the PV B-fragment (no shuffles, no smem P).
#define KP 80                          // Ks row stride (words): conflict-free LDS.128
#define VP 68                          // Vs row stride: conflict-free LDS.32 A-frags
#define KTW (64 * KP)                  // 5120 words
#define VTW (64 * VP)                  // 4352 words
#define ATTN_SMEM ((2 * KTW + 2 * VTW) * 4)   // 75776 bytes

__global__ __launch_bounds__(256, 1)
void attn_tc_kernel()
{
    extern __shared__ uint32_t smw[];
    uint32_t* KsB[2] = { smw, smw + KTW };
    uint32_t* VsB[2] = { smw + 2 * KTW, smw + 2 * KTW + VTW };

    const int tid  = threadIdx.x;
    const int lane = tid & 31;
    const int w    = tid >> 5;
    const int cq   = lane >> 2;
    const int j    = lane & 3;
    const int bh   = blockIdx.y;
    const int q0   = blockIdx.x * 256;

    const float*  Qg = g_Q + ((size_t)bh * S_ + q0) * DK_;
    const float4* Kg = (const float4*)(g_K + (size_t)bh * S_ * DK_);
    const float4* Vg = (const float4*)(g_V + (size_t)bh * S_ * DK_);

    // ---- Q fragments in registers (k-permuted: slot j -> g*16+4j+c) --------
    uint4 Qf[2][4][2];
#pragma unroll
    for (int mi = 0; mi < 2; mi++) {
        int row = w * 32 + mi * 16 + cq;
#pragma unroll
        for (int g = 0; g < 4; g++) {
            Qf[mi][g][0] = cvt4(*(const float4*)&Qg[(size_t)row * DK_ + g * 16 + 4 * j]);
            Qf[mi][g][1] = cvt4(*(const float4*)&Qg[(size_t)(row + 8) * DK_ + g * 16 + 4 * j]);
        }
    }

    // ---- prologue: tile 0 -> buf 0 -----------------------------------------
    {
#pragma unroll
        for (int i = 0; i < 4; i++) {
            int idx = tid + i * 256;
            int r = idx >> 4, c4 = idx & 15;
            *(uint4*)&KsB[0][r * KP + c4 * 4] = cvt4(Kg[idx]);
            *(uint4*)&VsB[0][r * VP + c4 * 4] = cvt4(Vg[idx]);
        }
    }
    __syncthreads();

    float m_[2][2], l_[2][2];
#pragma unroll
    for (int a = 0; a < 2; a++)
#pragma unroll
        for (int b = 0; b < 2; b++) { m_[a][b] = -1e30f; l_[a][b] = 0.0f; }

    // O^T accumulators: o[dt][qt][.]: rows d = dt*16+cq(+8), cols q = qt*8+2j(+1)
    float o[4][4][4];
#pragma unroll
    for (int dt = 0; dt < 4; dt++)
#pragma unroll
        for (int qt = 0; qt < 4; qt++)
#pragma unroll
            for (int c = 0; c < 4; c++) o[dt][qt][c] = 0.0f;

    const int NT = S_ / 64;
    for (int kt = 0; kt < NT; kt++) {
        const int p = kt & 1;
        const uint32_t* Ks = KsB[p];
        const uint32_t* Vs = VsB[p];
        const bool pf = (kt + 1 < NT);

        // prefetch K(kt+1) to regs (latency hidden behind S-phase)
        float4 kr[4];
        if (pf) {
#pragma unroll
            for (int i = 0; i < 4; i++) kr[i] = Kg[(kt + 1) * 1024 + tid + i * 256];
        }

        // ---- S = Q K^T ------------------------------------------------------
        float s[2][8][4];
#pragma unroll
        for (int mi = 0; mi < 2; mi++)
#pragma unroll
            for (int t = 0; t < 8; t++)
#pragma unroll
                for (int c = 0; c < 4; c++) s[mi][t][c] = 0.0f;

#pragma unroll
        for (int g = 0; g < 4; g++) {
#pragma unroll
            for (int t = 0; t < 8; t++) {
                uint4 kv = *(const uint4*)&Ks[(t * 8 + cq) * KP + g * 16 + 4 * j];
#pragma unroll
                for (int mi = 0; mi < 2; mi++) {
                    mma_tf32(s[mi][t], Qf[mi][g][0].x, Qf[mi][g][1].x,
                             Qf[mi][g][0].y, Qf[mi][g][1].y, kv.x, kv.y);
                    mma_tf32(s[mi][t], Qf[mi][g][0].z, Qf[mi][g][1].z,
                             Qf[mi][g][0].w, Qf[mi][g][1].w, kv.z, kv.w);
                }
            }
        }

        // store K prefetch, start V prefetch
        float4 vr[4];
        if (pf) {
#pragma unroll
            for (int i = 0; i < 4; i++) {
                int idx = tid + i * 256;
                *(uint4*)&KsB[1 - p][(idx >> 4) * KP + (idx & 15) * 4] = cvt4(kr[i]);
            }
#pragma unroll
            for (int i = 0; i < 4; i++) vr[i] = Vg[(kt + 1) * 1024 + tid + i * 256];
        }

        // ---- online softmax (rows: mi*16 + half*8 + cq) ---------------------
        float aown[2][2];
#pragma unroll
        for (int mi = 0; mi < 2; mi++) {
#pragma unroll
            for (int half = 0; half < 2; half++) {
                const int c0 = half * 2;
                float mx = s[mi][0][c0];
#pragma unroll
                for (int t = 0; t < 8; t++)
                    mx = fmaxf(mx, fmaxf(s[mi][t][c0], s[mi][t][c0 + 1]));
                mx = fmaxf(mx, __shfl_xor_sync(0xffffffffu, mx, 1));
                mx = fmaxf(mx, __shfl_xor_sync(0xffffffffu, mx, 2));
                float mn = fmaxf(m_[mi][half], mx);
                float al = __expf(m_[mi][half] - mn);
                m_[mi][half] = mn;
                aown[mi][half] = al;
                float rs = 0.0f;
#pragma unroll
                for (int t = 0; t < 8; t++) {
                    uint32_t e0 = f2tf(__expf(s[mi][t][c0] - mn));
                    uint32_t e1 = f2tf(__expf(s[mi][t][c0 + 1] - mn));
                    s[mi][t][c0]     = __uint_as_float(e0);
                    s[mi][t][c0 + 1] = __uint_as_float(e1);
                    rs += __uint_as_float(e0) + __uint_as_float(e1);
                }
                rs += __shfl_xor_sync(0xffffffffu, rs, 1);
                rs += __shfl_xor_sync(0xffffffffu, rs, 2);
                l_[mi][half] = l_[mi][half] * al + rs;
            }
        }

        // broadcast alphas to O's q-columns: q-rowidx 2j+c owned by lane (2j+c)*4+j
        float aO[4][2];
#pragma unroll
        for (int qt = 0; qt < 4; qt++) {
            float av = aown[qt >> 1][qt & 1];
            aO[qt][0] = __shfl_sync(0xffffffffu, av, ((2 * j) << 2) | j);
            aO[qt][1] = __shfl_sync(0xffffffffu, av, ((2 * j + 1) << 2) | j);
        }
#pragma unroll
        for (int dt = 0; dt < 4; dt++)
#pragma unroll
            for (int qt = 0; qt < 4; qt++) {
                o[dt][qt][0] *= aO[qt][0];
                o[dt][qt][1] *= aO[qt][1];
                o[dt][qt][2] *= aO[qt][0];
                o[dt][qt][3] *= aO[qt][1];
            }

        // ---- O^T += V^T P^T  (kv-permutation j->2j, j+4->2j+1) --------------
#pragma unroll
        for (int kb = 0; kb < 8; kb++) {
#pragma unroll
            for (int dt = 0; dt < 4; dt++) {
                const uint32_t* vrow = &Vs[(kb * 8 + 2 * j) * VP + dt * 16 + cq];
                uint32_t a0 = vrow[0];
                uint32_t a1 = vrow[8];
                uint32_t a2 = vrow[VP];
                uint32_t a3 = vrow[VP + 8];
#pragma unroll
                for (int qt = 0; qt < 4; qt++) {
                    const int mi = qt >> 1, hf = qt & 1;
                    mma_tf32(o[dt][qt], a0, a1, a2, a3,
                             __float_as_uint(s[mi][kb][hf * 2]),
                             __float_as_uint(s[mi][kb][hf * 2 + 1]));
                }
            }
        }

        // store V prefetch
        if (pf) {
#pragma unroll
            for (int i = 0; i < 4; i++) {
                int idx = tid + i * 256;
                *(uint4*)&VsB[1 - p][(idx >> 4) * VP + (idx & 15) * 4] = cvt4(vr[i]);
            }
        }
        __syncthreads();
    }

    // ---- epilogue: AO[b*s][h*64 + d], O^T frag scatter ----------------------
    float lO[4][2];
#pragma unroll
    for (int qt = 0; qt < 4; qt++) {
        float lv = l_[qt >> 1][qt & 1];
        lO[qt][0] = 1.0f / __shfl_sync(0xffffffffu, lv, ((2 * j) << 2) | j);
        lO[qt][1] = 1.0f / __shfl_sync(0xffffffffu, lv, ((2 * j + 1) << 2) | j);
    }
    const int bb = bh / H_, hh = bh % H_;
#pragma unroll
    for (int qt = 0; qt < 4; qt++) {
#pragma unroll
        for (int c = 0; c < 2; c++) {
            int q = q0 + w * 32 + (qt >> 1) * 16 + (qt & 1) * 8 + 2 * j + c;
            float* dst = &g_AO[(size_t)(bb * S_ + q) * E_ + hh * DK_];
#pragma unroll
            for (int dt = 0; dt < 4; dt++) {
                dst[dt * 16 + cq]     = o[dt][qt][c]     * lO[qt][c];
                dst[dt * 16 + cq + 8] = o[dt][qt][c + 2] * lO[qt][c];
            }
        }
    }
}

// ---------------- launch -----------------------------------------------------
extern "C" void kernel_launch(void* const* d_in, const int* in_sizes, int n_in,
                              void* d_out, int out_size)
{
    (void)in_sizes; (void)n_in; (void)out_size;
    const float* X  = (const float*)d_in[0];
    const float* Wq = (const float*)d_in[1];
    const float* Wk = (const float*)d_in[2];
    const float* Wv = (const float*)d_in[3];
    const float* Wo = (const float*)d_in[4];
    float* out = (float*)d_out;

    cudaFuncSetAttribute(attn_tc_kernel,
                         cudaFuncAttributeMaxDynamicSharedMemorySize, ATTN_SMEM);

    // Stage 1: Q/K/V projections (head-major scatter, Q pre-scaled by 1/8)
    gemm_tc<<<dim3(E_ / 128, ROWS_ / 128, 3), 256>>>(X, Wq, Wk, Wv, nullptr, 1);
    // Stage 2: tf32 mma flash attention
    attn_tc_kernel<<<dim3(S_ / 256, BH_), 256, ATTN_SMEM>>>();
    // Stage 3: output projection AO @ Wo -> out
    gemm_tc<<<dim3(E_ / 128, ROWS_ / 128, 1), 256>>>(nullptr, Wo, nullptr, nullptr, out, 0);
}

// round 5
// speedup vs baseline: 1.1393x; 1.1393x over previous
#include <cuda_runtime.h>
#include <cuda_bf16.h>
#include <cstdint>
#include <math.h>

// Problem constants
#define B_   2
#define S_   4096
#define E_   768
#define H_   12
#define DK_  64
#define BH_  (B_ * H_)          // 24
#define ROWS_ (B_ * S_)         // 8192

// ---------------- scratch (device globals; no allocation allowed) -----------
__device__ float g_X[ROWS_ * E_];        // tf32-rounded input
__device__ float g_Wq[E_ * E_];          // tf32-rounded weights
__device__ float g_Wk[E_ * E_];
__device__ float g_Wv[E_ * E_];
__device__ float g_Wo[E_ * E_];
__device__ float g_Q[BH_ * S_ * DK_];    // [bh][s][d], pre-scaled by 1/8, tf32
__device__ float g_K[BH_ * S_ * DK_];    // tf32
__device__ float g_V[BH_ * S_ * DK_];    // tf32
__device__ float g_AO[ROWS_ * E_];       // attention output, tf32

// ---------------- helpers ----------------------------------------------------
__device__ __forceinline__ uint32_t f2tf(float x) {
    uint32_t u;
    asm("cvt.rna.tf32.f32 %0, %1;" : "=r"(u) : "f"(x));
    return u;
}
__device__ __forceinline__ uint4 cvt4(float4 v) {
    return make_uint4(f2tf(v.x), f2tf(v.y), f2tf(v.z), f2tf(v.w));
}
__device__ __forceinline__ void mma_tf32(float* d,
                                         uint32_t a0, uint32_t a1,
                                         uint32_t a2, uint32_t a3,
                                         uint32_t b0, uint32_t b1) {
    asm volatile(
        "mma.sync.aligned.m16n8k8.row.col.f32.tf32.tf32.f32 "
        "{%0,%1,%2,%3}, {%4,%5,%6,%7}, {%8,%9}, {%0,%1,%2,%3};"
        : "+f"(d[0]), "+f"(d[1]), "+f"(d[2]), "+f"(d[3])
        : "r"(a0), "r"(a1), "r"(a2), "r"(a3), "r"(b0), "r"(b1));
}
__device__ __forceinline__ void cpa16(uint32_t dst, const void* src) {
    asm volatile("cp.async.ca.shared.global [%0], [%1], 16;"
                 :: "r"(dst), "l"(src) : "memory");
}
#define CP_COMMIT() asm volatile("cp.async.commit_group;" ::: "memory")
#define CP_WAIT0()  asm volatile("cp.async.wait_group 0;" ::: "memory")

// ---------------- prepass: round X + weights to tf32 in gmem ----------------
#define NX4 (ROWS_ * E_ / 4)             // 1572864
#define NW4 (E_ * E_ / 4)                // 147456

__global__ __launch_bounds__(256)
void prepass(const float* __restrict__ X,
             const float* __restrict__ Wq, const float* __restrict__ Wk,
             const float* __restrict__ Wv, const float* __restrict__ Wo)
{
    int i = blockIdx.x * blockDim.x + threadIdx.x;
    if (i < NX4) {
        ((uint4*)g_X)[i] = cvt4(((const float4*)X)[i]);
    } else {
        int r = i - NX4;
        int wsel = r / NW4;
        r = r % NW4;
        const float4* src = (wsel == 0) ? (const float4*)Wq
                          : (wsel == 1) ? (const float4*)Wk
                          : (wsel == 2) ? (const float4*)Wv
                                        : (const float4*)Wo;
        uint4* dst = (wsel == 0) ? (uint4*)g_Wq
                   : (wsel == 1) ? (uint4*)g_Wk
                   : (wsel == 2) ? (uint4*)g_Wv
                                 : (uint4*)g_Wo;
        dst[r] = cvt4(src[r]);
    }
}

// ---------------- GEMM: C = A[8192,768] @ W[768,768] (tf32 mma) -------------
// BM=128, BN=128, BK=16, double-buffered smem, cp.async, no cvt in loop.
#define AP 20
#define BP 136

__global__ __launch_bounds__(256, 2)
void gemm_tc(float* __restrict__ Out, int mode)
{
    __shared__ uint32_t As[2][128 * AP];
    __shared__ uint32_t Bs[2][16 * BP];

    const float* A;
    const float* W;
    float* Dst = nullptr;
    float scale = 1.0f;
    if (mode == 1) {
        A = g_X;
        int z = blockIdx.z;
        W   = (z == 0) ? g_Wq : (z == 1) ? g_Wk : g_Wv;
        Dst = (z == 0) ? g_Q  : (z == 1) ? g_K  : g_V;
        if (z == 0) scale = 0.125f;
    } else {
        A = g_AO;
        W = g_Wo;
    }

    const int tid  = threadIdx.x;
    const int lane = tid & 31;
    const int wid  = tid >> 5;
    const int wm   = wid >> 2;
    const int wn   = wid & 3;
    const int cq   = lane >> 2;
    const int j    = lane & 3;
    const int row0 = blockIdx.y * 128;
    const int col0 = blockIdx.x * 128;

    const int ar0 = tid >> 2, ac4 = tid & 3;
    const int bk0 = tid >> 5, bc4 = tid & 31;

    const uint32_t as_base = (uint32_t)__cvta_generic_to_shared(&As[0][0]);
    const uint32_t bs_base = (uint32_t)__cvta_generic_to_shared(&Bs[0][0]);
    const uint32_t as_sz = 128 * AP * 4;
    const uint32_t bs_sz = 16 * BP * 4;

    float acc[4][4][4];
#pragma unroll
    for (int mi = 0; mi < 4; mi++)
#pragma unroll
        for (int ni = 0; ni < 4; ni++)
#pragma unroll
            for (int q = 0; q < 4; q++) acc[mi][ni][q] = 0.0f;

    // prologue: tile k0=0 -> buf 0
#pragma unroll
    for (int i = 0; i < 2; i++) {
        int r = ar0 + i * 64;
        cpa16(as_base + (r * AP + ac4 * 4) * 4,
              &A[(size_t)(row0 + r) * E_ + ac4 * 4]);
    }
#pragma unroll
    for (int i = 0; i < 2; i++) {
        int kr = bk0 + i * 8;
        cpa16(bs_base + (kr * BP + bc4 * 4) * 4,
              &W[(size_t)kr * E_ + col0 + bc4 * 4]);
    }
    CP_COMMIT();
    CP_WAIT0();
    __syncthreads();

    for (int k0 = 0; k0 < E_; k0 += 16) {
        const int p = (k0 >> 4) & 1;
        const bool pf = (k0 + 16 < E_);
        if (pf) {
#pragma unroll
            for (int i = 0; i < 2; i++) {
                int r = ar0 + i * 64;
                cpa16(as_base + (1 - p) * as_sz + (r * AP + ac4 * 4) * 4,
                      &A[(size_t)(row0 + r) * E_ + k0 + 16 + ac4 * 4]);
            }
#pragma unroll
            for (int i = 0; i < 2; i++) {
                int kr = bk0 + i * 8;
                cpa16(bs_base + (1 - p) * bs_sz + (kr * BP + bc4 * 4) * 4,
                      &W[(size_t)(k0 + 16 + kr) * E_ + col0 + bc4 * 4]);
            }
            CP_COMMIT();
        }

#pragma unroll
        for (int ks = 0; ks < 16; ks += 8) {
            uint32_t af[4][4], bf[4][2];
#pragma unroll
            for (int mi = 0; mi < 4; mi++) {
                int row = wm * 64 + mi * 16 + cq;
                int ka  = ks + j;
                af[mi][0] = As[p][row * AP + ka];
                af[mi][1] = As[p][(row + 8) * AP + ka];
                af[mi][2] = As[p][row * AP + ka + 4];
                af[mi][3] = As[p][(row + 8) * AP + ka + 4];
            }
#pragma unroll
            for (int ni = 0; ni < 4; ni++) {
                int col = wn * 32 + ni * 8 + cq;
                bf[ni][0] = Bs[p][(ks + j) * BP + col];
                bf[ni][1] = Bs[p][(ks + 4 + j) * BP + col];
            }
#pragma unroll
            for (int mi = 0; mi < 4; mi++)
#pragma unroll
                for (int ni = 0; ni < 4; ni++)
                    mma_tf32(acc[mi][ni], af[mi][0], af[mi][1], af[mi][2], af[mi][3],
                             bf[ni][0], bf[ni][1]);
        }

        if (pf) CP_WAIT0();
        __syncthreads();
    }

#pragma unroll
    for (int mi = 0; mi < 4; mi++) {
#pragma unroll
        for (int ni = 0; ni < 4; ni++) {
            int r_   = row0 + wm * 64 + mi * 16 + cq;
            int col  = col0 + wn * 32 + ni * 8 + 2 * j;
            if (mode == 1) {
                // store tf32-rounded (consumed raw by attention MMAs)
                float2 v0 = make_float2(
                    __uint_as_float(f2tf(acc[mi][ni][0] * scale)),
                    __uint_as_float(f2tf(acc[mi][ni][1] * scale)));
                float2 v1 = make_float2(
                    __uint_as_float(f2tf(acc[mi][ni][2] * scale)),
                    __uint_as_float(f2tf(acc[mi][ni][3] * scale)));
                int h  = col >> 6;
                int d0 = col & 63;
                int b0b = r_ >> 12, s0s = r_ & (S_ - 1);
                *(float2*)&Dst[(((size_t)b0b * H_ + h) * S_ + s0s) * DK_ + d0] = v0;
                int r1 = r_ + 8;
                int b1b = r1 >> 12, s1s = r1 & (S_ - 1);
                *(float2*)&Dst[(((size_t)b1b * H_ + h) * S_ + s1s) * DK_ + d0] = v1;
            } else {
                *(float2*)&Out[(size_t)r_ * E_ + col] =
                    make_float2(acc[mi][ni][0], acc[mi][ni][1]);
                *(float2*)&Out[(size_t)(r_ + 8) * E_ + col] =
                    make_float2(acc[mi][ni][2], acc[mi][ni][3]);
            }
        }
    }
}

// ---------------- flash attention v3: cp.async, no cvt, Q-in-regs ------------
// CTA: 256 q-rows x 1 head, 8 warps x 32 q-rows. KV tile 64, double-buffered.
// PV computes O^T = V^T P^T (kv-permutation) so S C-frag == PV B-frag.
#define KP 80
#define VP 68
#define KTW (64 * KP)
#define VTW (64 * VP)
#define ATTN_SMEM ((2 * KTW + 2 * VTW) * 4)   // 75776 bytes

__global__ __launch_bounds__(256, 1)
void attn_tc_kernel()
{
    extern __shared__ uint32_t smw[];
    uint32_t* KsB[2] = { smw, smw + KTW };
    uint32_t* VsB[2] = { smw + 2 * KTW, smw + 2 * KTW + VTW };
    uint32_t ksb[2], vsb[2];
#pragma unroll
    for (int i = 0; i < 2; i++) {
        ksb[i] = (uint32_t)__cvta_generic_to_shared(KsB[i]);
        vsb[i] = (uint32_t)__cvta_generic_to_shared(VsB[i]);
    }

    const int tid  = threadIdx.x;
    const int lane = tid & 31;
    const int w    = tid >> 5;
    const int cq   = lane >> 2;
    const int j    = lane & 3;
    const int bh   = blockIdx.y;
    const int q0   = blockIdx.x * 256;

    const float* Qg  = g_Q + ((size_t)bh * S_ + q0) * DK_;
    const float* KgF = g_K + (size_t)bh * S_ * DK_;
    const float* VgF = g_V + (size_t)bh * S_ * DK_;

    // issue tile 0 -> buf 0 (overlaps with Q frag loads below)
#pragma unroll
    for (int i = 0; i < 4; i++) {
        int idx = tid + i * 256;
        int r = idx >> 4, c4 = idx & 15;
        cpa16(ksb[0] + (r * KP + c4 * 4) * 4, KgF + idx * 4);
        cpa16(vsb[0] + (r * VP + c4 * 4) * 4, VgF + idx * 4);
    }
    CP_COMMIT();

    // Q fragments in registers (pre-rounded tf32; k-permuted slot j -> 4j+c)
    uint4 Qf[2][4][2];
#pragma unroll
    for (int mi = 0; mi < 2; mi++) {
        int row = w * 32 + mi * 16 + cq;
#pragma unroll
        for (int g = 0; g < 4; g++) {
            Qf[mi][g][0] = *(const uint4*)&Qg[(size_t)row * DK_ + g * 16 + 4 * j];
            Qf[mi][g][1] = *(const uint4*)&Qg[(size_t)(row + 8) * DK_ + g * 16 + 4 * j];
        }
    }

    CP_WAIT0();
    __syncthreads();

    float m_[2][2], l_[2][2];
#pragma unroll
    for (int a = 0; a < 2; a++)
#pragma unroll
        for (int b = 0; b < 2; b++) { m_[a][b] = -1e30f; l_[a][b] = 0.0f; }

    // O^T accumulators: rows d = dt*16+cq(+8), cols q = qt*8+2j(+1)
    float o[4][4][4];
#pragma unroll
    for (int dt = 0; dt < 4; dt++)
#pragma unroll
        for (int qt = 0; qt < 4; qt++)
#pragma unroll
            for (int c = 0; c < 4; c++) o[dt][qt][c] = 0.0f;

    const int NT = S_ / 64;
    for (int kt = 0; kt < NT; kt++) {
        const int p = kt & 1;
        const uint32_t* Ks = KsB[p];
        const uint32_t* Vs = VsB[p];
        const bool pf = (kt + 1 < NT);

        // async-load next tile into other buffer (overlaps all compute below)
        if (pf) {
            const float* ksrc = KgF + (size_t)(kt + 1) * 4096;
            const float* vsrc = VgF + (size_t)(kt + 1) * 4096;
#pragma unroll
            for (int i = 0; i < 4; i++) {
                int idx = tid + i * 256;
                int r = idx >> 4, c4 = idx & 15;
                cpa16(ksb[1 - p] + (r * KP + c4 * 4) * 4, ksrc + idx * 4);
                cpa16(vsb[1 - p] + (r * VP + c4 * 4) * 4, vsrc + idx * 4);
            }
            CP_COMMIT();
        }

        // ---- S = Q K^T ------------------------------------------------------
        float s[2][8][4];
#pragma unroll
        for (int mi = 0; mi < 2; mi++)
#pragma unroll
            for (int t = 0; t < 8; t++)
#pragma unroll
                for (int c = 0; c < 4; c++) s[mi][t][c] = 0.0f;

#pragma unroll
        for (int g = 0; g < 4; g++) {
#pragma unroll
            for (int t = 0; t < 8; t++) {
                uint4 kv = *(const uint4*)&Ks[(t * 8 + cq) * KP + g * 16 + 4 * j];
#pragma unroll
                for (int mi = 0; mi < 2; mi++) {
                    mma_tf32(s[mi][t], Qf[mi][g][0].x, Qf[mi][g][1].x,
                             Qf[mi][g][0].y, Qf[mi][g][1].y, kv.x, kv.y);
                    mma_tf32(s[mi][t], Qf[mi][g][0].z, Qf[mi][g][1].z,
                             Qf[mi][g][0].w, Qf[mi][g][1].w, kv.z, kv.w);
                }
            }
        }

        // ---- online softmax (rows: mi*16 + half*8 + cq) ---------------------
        float aown[2][2];
#pragma unroll
        for (int mi = 0; mi < 2; mi++) {
#pragma unroll
            for (int half = 0; half < 2; half++) {
                const int c0 = half * 2;
                float mx = s[mi][0][c0];
#pragma unroll
                for (int t = 0; t < 8; t++)
                    mx = fmaxf(mx, fmaxf(s[mi][t][c0], s[mi][t][c0 + 1]));
                mx = fmaxf(mx, __shfl_xor_sync(0xffffffffu, mx, 1));
                mx = fmaxf(mx, __shfl_xor_sync(0xffffffffu, mx, 2));
                float mn = fmaxf(m_[mi][half], mx);
                float al = __expf(m_[mi][half] - mn);
                m_[mi][half] = mn;
                aown[mi][half] = al;
                float rs = 0.0f;
#pragma unroll
                for (int t = 0; t < 8; t++) {
                    uint32_t e0 = f2tf(__expf(s[mi][t][c0] - mn));
                    uint32_t e1 = f2tf(__expf(s[mi][t][c0 + 1] - mn));
                    s[mi][t][c0]     = __uint_as_float(e0);
                    s[mi][t][c0 + 1] = __uint_as_float(e1);
                    rs += __uint_as_float(e0) + __uint_as_float(e1);
                }
                rs += __shfl_xor_sync(0xffffffffu, rs, 1);
                rs += __shfl_xor_sync(0xffffffffu, rs, 2);
                l_[mi][half] = l_[mi][half] * al + rs;
            }
        }

        // broadcast alphas to O^T q-columns
        float aO[4][2];
#pragma unroll
        for (int qt = 0; qt < 4; qt++) {
            float av = aown[qt >> 1][qt & 1];
            aO[qt][0] = __shfl_sync(0xffffffffu, av, ((2 * j) << 2) | j);
            aO[qt][1] = __shfl_sync(0xffffffffu, av, ((2 * j + 1) << 2) | j);
        }
#pragma unroll
        for (int dt = 0; dt < 4; dt++)
#pragma unroll
            for (int qt = 0; qt < 4; qt++) {
                o[dt][qt][0] *= aO[qt][0];
                o[dt][qt][1] *= aO[qt][1];
                o[dt][qt][2] *= aO[qt][0];
                o[dt][qt][3] *= aO[qt][1];
            }

        // ---- O^T += V^T P^T  (kv-permutation j->2j, j+4->2j+1) --------------
#pragma unroll
        for (int kb = 0; kb < 8; kb++) {
#pragma unroll
            for (int dt = 0; dt < 4; dt++) {
                const uint32_t* vrow = &Vs[(kb * 8 + 2 * j) * VP + dt * 16 + cq];
                uint32_t a0 = vrow[0];
                uint32_t a1 = vrow[8];
                uint32_t a2 = vrow[VP];
                uint32_t a3 = vrow[VP + 8];
#pragma unroll
                for (int qt = 0; qt < 4; qt++) {
                    const int mi = qt >> 1, hf = qt & 1;
                    mma_tf32(o[dt][qt], a0, a1, a2, a3,
                             __float_as_uint(s[mi][kb][hf * 2]),
                             __float_as_uint(s[mi][kb][hf * 2 + 1]));
                }
            }
        }

        if (pf) CP_WAIT0();
        __syncthreads();
    }

    // ---- epilogue: AO[b*s][h*64 + d], tf32-rounded --------------------------
    float lO[4][2];
#pragma unroll
    for (int qt = 0; qt < 4; qt++) {
        float lv = l_[qt >> 1][qt & 1];
        lO[qt][0] = 1.0f / __shfl_sync(0xffffffffu, lv, ((2 * j) << 2) | j);
        lO[qt][1] = 1.0f / __shfl_sync(0xffffffffu, lv, ((2 * j + 1) << 2) | j);
    }
    const int bb = bh / H_, hh = bh % H_;
#pragma unroll
    for (int qt = 0; qt < 4; qt++) {
#pragma unroll
        for (int c = 0; c < 2; c++) {
            int q = q0 + w * 32 + (qt >> 1) * 16 + (qt & 1) * 8 + 2 * j + c;
            float* dst = &g_AO[(size_t)(bb * S_ + q) * E_ + hh * DK_];
#pragma unroll
            for (int dt = 0; dt < 4; dt++) {
                dst[dt * 16 + cq] =
                    __uint_as_float(f2tf(o[dt][qt][c] * lO[qt][c]));
                dst[dt * 16 + cq + 8] =
                    __uint_as_float(f2tf(o[dt][qt][c + 2] * lO[qt][c]));
            }
        }
    }
}

// ---------------- launch -----------------------------------------------------
extern "C" void kernel_launch(void* const* d_in, const int* in_sizes, int n_in,
                              void* d_out, int out_size)
{
    (void)in_sizes; (void)n_in; (void)out_size;
    const float* X  = (const float*)d_in[0];
    const float* Wq = (const float*)d_in[1];
    const float* Wk = (const float*)d_in[2];
    const float* Wv = (const float*)d_in[3];
    const float* Wo = (const float*)d_in[4];
    float* out = (float*)d_out;

    cudaFuncSetAttribute(attn_tc_kernel,
                         cudaFuncAttributeMaxDynamicSharedMemorySize, ATTN_SMEM);

    // Stage 0: round X + weights to tf32 once
    prepass<<<(NX4 + 4 * NW4) / 256, 256>>>(X, Wq, Wk, Wv, Wo);
    // Stage 1: Q/K/V projections (head-major scatter, Q pre-scaled by 1/8)
    gemm_tc<<<dim3(E_ / 128, ROWS_ / 128, 3), 256>>>(nullptr, 1);
    // Stage 2: tf32 mma flash attention
    attn_tc_kernel<<<dim3(S_ / 256, BH_), 256, ATTN_SMEM>>>();
    // Stage 3: output projection AO @ Wo -> out
    gemm_tc<<<dim3(E_ / 128, ROWS_ / 128, 1), 256>>>(out, 0);
}